// round 13
// baseline (speedup 1.0000x reference)
#include <cuda_runtime.h>
#include <cstdint>

#define B_  32
#define T_  2048
#define IN_ 512
#define H_  256
#define NG  32      // groups of 8 presynaptic neurons
#define NP  256     // patterns per group (2^8)
#define NCH 32      // T_/64 proj chunks per batch

#define NSCAN 32    // scan CTAs (one per batch)
#define NWORK 116   // persistent GEMM worker CTAs
#define NJOBS 2048  // (B_*T_/GM) * 2 n-halves

// Scratch (allocation-free rule: __device__ globals)
__device__ float g_proj[(size_t)B_ * T_ * H_];        // 64 MB input projection
__device__ float g_Vt[H_ * H_];                       // Vt[j][h] = V[h][j]
__device__ float g_tab[(size_t)NG * NP * H_];         // 8 MB group subset-sum table (L2-pinned)
__device__ unsigned g_flag[B_ * NCH];                 // producer->consumer chunk flags

// createpolicy: evict_last fraction 1.0 (uniform, hoisted by ptxas)
__device__ __forceinline__ uint64_t mk_policy(void) {
    uint64_t pol;
    asm("createpolicy.fractional.L2::evict_last.b64 %0, 1.0;" : "=l"(pol));
    return pol;
}

// L2 evict_last table load (pin table rows in L2 against GEMM streaming)
__device__ __forceinline__ float4 ldg_tab(const void* p, uint64_t pol) {
    float4 v;
    asm volatile("ld.global.nc.L2::cache_hint.v4.f32 {%0,%1,%2,%3}, [%4], %5;"
                 : "=f"(v.x), "=f"(v.y), "=f"(v.z), "=f"(v.w)
                 : "l"(p), "l"(pol));
    return v;
}

// ---------------------------------------------------------------------------
// Setup kernels
// ---------------------------------------------------------------------------
__global__ void transpose_V(const float* __restrict__ V) {
    int j = blockIdx.x;
    int h = threadIdx.x;
    g_Vt[j * H_ + h] = V[h * H_ + j];
}

// tab[g][p][h] = sum_{i: bit i of p} Vt[8g+i][h]   (ascending i)
__global__ void build_tab(void) {
    const int blk = blockIdx.x;          // 0..8191
    const int g = blk >> 8;
    const int p = blk & 255;
    const int h = threadIdx.x;
    float s = 0.0f;
    #pragma unroll
    for (int i = 0; i < 8; i++)
        if ((p >> i) & 1)
            s = __fadd_rn(s, g_Vt[(g * 8 + i) * H_ + h]);
    g_tab[((size_t)g * NP + p) * H_ + h] = s;
}

__global__ void init_flags(void) {
    g_flag[threadIdx.x] = 0u;
}

// ---------------------------------------------------------------------------
// chunk-ready spin (acquire)
// ---------------------------------------------------------------------------
__device__ __forceinline__ void wait_chunk(const unsigned* f) {
    unsigned v;
    do {
        asm volatile("ld.acquire.gpu.global.u32 %0, [%1];"
                     : "=r"(v) : "l"(f) : "memory");
    } while (v < 2u);
}

// ---------------------------------------------------------------------------
// Fused persistent kernel.
//   CTA 0..31   : LIF scan for batch = blockIdx.x (R7 structure)
//   CTA 32..147 : GEMM workers, grid-stride over NJOBS tile jobs
// ---------------------------------------------------------------------------
#define GM 64
#define GN 128
#define GK 16

__global__ __launch_bounds__(256, 1) void fused_kernel(
    const float* __restrict__ x, const float* __restrict__ W,
    const float* __restrict__ bia,
    const float* __restrict__ b_rec, float* __restrict__ out) {

    __shared__ float As[2][GK][GM];       // GEMM buffers (worker role)
    __shared__ float Bs[2][GK][GN];
    __shared__ float4 sp[2][4][64];       // scan partials (scan role)
    __shared__ unsigned sbits[2][8];

    const int cta = blockIdx.x;
    const int tid = threadIdx.x;

    if (cta >= NSCAN) {
        // =================== GEMM worker role ===================
        const int tx = tid & 15;
        const int ty = tid >> 4;
        const int lr = tid >> 2;
        const int lc = (tid & 3) * 4;

        for (int jj = cta - NSCAN; jj < NJOBS; jj += NWORK) {
            const int nt = jj & 1;
            const int b  = (jj >> 1) & 31;
            const int tc = jj >> 6;
            const size_t m0 = (size_t)b * T_ + (size_t)tc * GM;
            const int bn = nt * GN;

            float acc[4][8];
            #pragma unroll
            for (int i = 0; i < 4; i++)
                #pragma unroll
                for (int j = 0; j < 8; j++) acc[i][j] = 0.0f;

            float4 ra, rb0, rb1;
            ra  = __ldcs((const float4*)&x[(m0 + lr) * IN_ + lc]);
            rb0 = *(const float4*)&W[(size_t)(bn + lr) * IN_ + lc];
            rb1 = *(const float4*)&W[(size_t)(bn + 64 + lr) * IN_ + lc];
            As[0][lc + 0][lr] = ra.x;  As[0][lc + 1][lr] = ra.y;
            As[0][lc + 2][lr] = ra.z;  As[0][lc + 3][lr] = ra.w;
            Bs[0][lc + 0][lr] = rb0.x; Bs[0][lc + 1][lr] = rb0.y;
            Bs[0][lc + 2][lr] = rb0.z; Bs[0][lc + 3][lr] = rb0.w;
            Bs[0][lc + 0][lr + 64] = rb1.x; Bs[0][lc + 1][lr + 64] = rb1.y;
            Bs[0][lc + 2][lr + 64] = rb1.z; Bs[0][lc + 3][lr + 64] = rb1.w;
            __syncthreads();

            const int NT = IN_ / GK;   // 32
            for (int kt = 0; kt < NT; kt++) {
                const int cur = kt & 1, nxt = cur ^ 1;
                if (kt + 1 < NT) {
                    int k0 = (kt + 1) * GK + lc;
                    ra  = __ldcs((const float4*)&x[(m0 + lr) * IN_ + k0]);
                    rb0 = *(const float4*)&W[(size_t)(bn + lr) * IN_ + k0];
                    rb1 = *(const float4*)&W[(size_t)(bn + 64 + lr) * IN_ + k0];
                }
                #pragma unroll
                for (int kk = 0; kk < GK; kk++) {
                    float a[4], bb[8];
                    *(float4*)&a[0]  = *(const float4*)&As[cur][kk][ty * 4];
                    *(float4*)&bb[0] = *(const float4*)&Bs[cur][kk][tx * 8];
                    *(float4*)&bb[4] = *(const float4*)&Bs[cur][kk][tx * 8 + 4];
                    #pragma unroll
                    for (int i = 0; i < 4; i++)
                        #pragma unroll
                        for (int j = 0; j < 8; j++)
                            acc[i][j] = fmaf(a[i], bb[j], acc[i][j]);
                }
                if (kt + 1 < NT) {
                    As[nxt][lc + 0][lr] = ra.x;  As[nxt][lc + 1][lr] = ra.y;
                    As[nxt][lc + 2][lr] = ra.z;  As[nxt][lc + 3][lr] = ra.w;
                    Bs[nxt][lc + 0][lr] = rb0.x; Bs[nxt][lc + 1][lr] = rb0.y;
                    Bs[nxt][lc + 2][lr] = rb0.z; Bs[nxt][lc + 3][lr] = rb0.w;
                    Bs[nxt][lc + 0][lr + 64] = rb1.x; Bs[nxt][lc + 1][lr + 64] = rb1.y;
                    Bs[nxt][lc + 2][lr + 64] = rb1.z; Bs[nxt][lc + 3][lr + 64] = rb1.w;
                }
                __syncthreads();
            }

            float bv[8];
            #pragma unroll
            for (int j = 0; j < 8; j++) bv[j] = bia[bn + tx * 8 + j];
            #pragma unroll
            for (int i = 0; i < 4; i++) {
                size_t m = m0 + ty * 4 + i;
                float4 o0, o1;
                o0.x = acc[i][0] + bv[0]; o0.y = acc[i][1] + bv[1];
                o0.z = acc[i][2] + bv[2]; o0.w = acc[i][3] + bv[3];
                o1.x = acc[i][4] + bv[4]; o1.y = acc[i][5] + bv[5];
                o1.z = acc[i][6] + bv[6]; o1.w = acc[i][7] + bv[7];
                __stcs((float4*)&g_proj[m * H_ + bn + tx * 8],     o0);
                __stcs((float4*)&g_proj[m * H_ + bn + tx * 8 + 4], o1);
            }

            __syncthreads();
            if (tid == 0) {
                __threadfence();
                atomicAdd(&g_flag[b * NCH + tc], 1u);
            }
        }
        return;
    }

    // ======================= scan role (R7 structure) =======================
    const int b = cta;
    const int h = tid;
    const int wid = tid >> 5, lane = tid & 31;
    const int q = tid >> 6, u = tid & 63;

    const float* pb = g_proj + (size_t)b * T_ * H_;
    float* ob = out + (size_t)b * T_ * H_;
    const float brec = b_rec[h];
    const unsigned* fb = g_flag + b * NCH;
    const uint64_t pol = mk_policy();

    const char* tbase = (const char*)g_tab
                      + ((size_t)q * 8 * NP * H_ * 4)
                      + (size_t)u * 16;

    if (tid < 8) sbits[0][tid] = 0u;
    __syncthreads();

    if (tid == 0) wait_chunk(fb);
    __syncthreads();

    float mem = 0.0f, spk = 0.0f;
    int buf = 0;
    float p0 = __ldcs(&pb[h]);
    float p1 = __ldcs(&pb[H_ + h]);

    for (int t = 0; t < T_; t++) {
        const int tn = t + 2;
        if (tn < T_ && (tn & 63) == 0) {
            if (tid == 0) wait_chunk(fb + (tn >> 6));
            __syncthreads();
        }
        float p2 = (tn < T_) ? __ldcs(&pb[(size_t)tn * H_ + h]) : 0.0f;

        // ---- phase 1: table-row gather (groups ascending = j ascending) ----
        const unsigned wA = sbits[buf][2 * q];
        const unsigned wB = sbits[buf][2 * q + 1];
        float4 acc = make_float4(0.f, 0.f, 0.f, 0.f);
        #pragma unroll
        for (int i = 0; i < 8; i++) {
            unsigned pat = (i < 4) ? ((wA >> (8 * i)) & 0xFFu)
                                   : ((wB >> (8 * (i - 4))) & 0xFFu);
            const float4 v = ldg_tab(tbase + (((unsigned)i << 8) + pat) * 1024u, pol);
            acc.x = __fadd_rn(acc.x, v.x);
            acc.y = __fadd_rn(acc.y, v.y);
            acc.z = __fadd_rn(acc.z, v.z);
            acc.w = __fadd_rn(acc.w, v.w);
        }
        sp[buf][q][u] = acc;
        __syncthreads();   // A

        // ---- phase 2: combine quarters + LIF update ----
        const int uu = h >> 2, c = h & 3;
        const float r0 = ((const float*)&sp[buf][0][uu])[c];
        const float r1 = ((const float*)&sp[buf][1][uu])[c];
        const float r2 = ((const float*)&sp[buf][2][uu])[c];
        const float r3 = ((const float*)&sp[buf][3][uu])[c];
        float rec = __fadd_rn(__fadd_rn(r0, r1), __fadd_rn(r2, r3));
        rec = __fadd_rn(rec, brec);

        const float reset = (mem > 1.0f) ? 1.0f : 0.0f;
        const float in_ = __fadd_rn(p0, spk);
        mem = __fsub_rn(__fadd_rn(__fadd_rn(__fmul_rn(0.85f, mem), in_), rec), reset);
        const float s = (mem > 1.0f) ? 1.0f : 0.0f;
        __stcs(&ob[(size_t)t * H_ + h], s);

        const unsigned ball = __ballot_sync(0xFFFFFFFFu, s != 0.0f);
        const int nb = buf ^ 1;
        if (lane == 0) sbits[nb][wid] = ball;
        __syncthreads();   // B

        buf = nb; spk = s;
        p0 = p1; p1 = p2;
    }
}

// ---------------------------------------------------------------------------
extern "C" void kernel_launch(void* const* d_in, const int* in_sizes, int n_in,
                              void* d_out, int out_size) {
    const float* x     = (const float*)d_in[0];
    const float* W_in  = (const float*)d_in[1];
    const float* b_in  = (const float*)d_in[2];
    const float* V     = (const float*)d_in[3];
    const float* b_rec = (const float*)d_in[4];
    float* out = (float*)d_out;

    transpose_V<<<H_, H_>>>(V);
    build_tab<<<NG * NP, H_>>>();
    init_flags<<<1, B_ * NCH>>>();
    fused_kernel<<<NSCAN + NWORK, 256>>>(x, W_in, b_in, b_rec, out);
}

// round 14
// speedup vs baseline: 1.3358x; 1.3358x over previous
#include <cuda_runtime.h>
#include <cstdint>

#define B_  32
#define T_  2048
#define IN_ 512
#define H_  256
#define NG  32      // groups of 8 presynaptic neurons
#define NP  256     // patterns per group (2^8)
#define NCH 32      // T_/64 proj chunks per batch

#define NSCAN 32    // scan CTAs (one per batch)
#define NWORK 116   // persistent GEMM worker CTAs
#define NJOBS 2048  // (B_*T_/GM) * 2 n-halves

// Scratch (allocation-free rule: __device__ globals)
__device__ float g_proj[(size_t)B_ * T_ * H_];        // 64 MB input projection
__device__ float g_Vt[H_ * H_];                       // Vt[j][h] = V[h][j]
__device__ float g_tab[(size_t)NG * NP * H_];         // 8 MB group subset-sum table (L2-resident)
__device__ unsigned g_flag[B_ * NCH];                 // producer->consumer chunk flags

// ---------------------------------------------------------------------------
// Setup kernels
// ---------------------------------------------------------------------------
__global__ void transpose_V(const float* __restrict__ V) {
    int j = blockIdx.x;
    int h = threadIdx.x;
    g_Vt[j * H_ + h] = V[h * H_ + j];
}

// tab[g][p][h] = sum_{i: bit i of p} Vt[8g+i][h]   (ascending i)
__global__ void build_tab(void) {
    const int blk = blockIdx.x;          // 0..8191
    const int g = blk >> 8;
    const int p = blk & 255;
    const int h = threadIdx.x;
    float s = 0.0f;
    #pragma unroll
    for (int i = 0; i < 8; i++)
        if ((p >> i) & 1)
            s = __fadd_rn(s, g_Vt[(g * 8 + i) * H_ + h]);
    g_tab[((size_t)g * NP + p) * H_ + h] = s;
}

__global__ void init_flags(void) {
    g_flag[threadIdx.x] = 0u;
}

// ---------------------------------------------------------------------------
// chunk-ready spin (acquire)
// ---------------------------------------------------------------------------
__device__ __forceinline__ void wait_chunk(const unsigned* f) {
    unsigned v;
    do {
        asm volatile("ld.acquire.gpu.global.u32 %0, [%1];"
                     : "=r"(v) : "l"(f) : "memory");
    } while (v < 2u);
}

// ---------------------------------------------------------------------------
// Fused persistent kernel.
//   CTA 0..31   : LIF scan for batch = blockIdx.x (R7 structure, untouched)
//   CTA 32..147 : GEMM workers with streaming (evict-first) cache ops
// ---------------------------------------------------------------------------
#define GM 64
#define GN 128
#define GK 16

__global__ __launch_bounds__(256, 1) void fused_kernel(
    const float* __restrict__ x, const float* __restrict__ W,
    const float* __restrict__ bia,
    const float* __restrict__ b_rec, float* __restrict__ out) {

    __shared__ float As[2][GK][GM];       // GEMM buffers (worker role)
    __shared__ float Bs[2][GK][GN];
    __shared__ float4 sp[2][4][64];       // scan partials (scan role)
    __shared__ unsigned sbits[2][8];

    const int cta = blockIdx.x;
    const int tid = threadIdx.x;

    if (cta >= NSCAN) {
        // =================== GEMM worker role ===================
        const int tx = tid & 15;
        const int ty = tid >> 4;
        const int lr = tid >> 2;
        const int lc = (tid & 3) * 4;

        for (int jj = cta - NSCAN; jj < NJOBS; jj += NWORK) {
            const int nt = jj & 1;
            const int b  = (jj >> 1) & 31;
            const int tc = jj >> 6;
            const size_t m0 = (size_t)b * T_ + (size_t)tc * GM;
            const int bn = nt * GN;

            float acc[4][8];
            #pragma unroll
            for (int i = 0; i < 4; i++)
                #pragma unroll
                for (int j = 0; j < 8; j++) acc[i][j] = 0.0f;

            float4 ra, rb0, rb1;
            ra  = __ldcs((const float4*)&x[(m0 + lr) * IN_ + lc]);
            rb0 = *(const float4*)&W[(size_t)(bn + lr) * IN_ + lc];
            rb1 = *(const float4*)&W[(size_t)(bn + 64 + lr) * IN_ + lc];
            As[0][lc + 0][lr] = ra.x;  As[0][lc + 1][lr] = ra.y;
            As[0][lc + 2][lr] = ra.z;  As[0][lc + 3][lr] = ra.w;
            Bs[0][lc + 0][lr] = rb0.x; Bs[0][lc + 1][lr] = rb0.y;
            Bs[0][lc + 2][lr] = rb0.z; Bs[0][lc + 3][lr] = rb0.w;
            Bs[0][lc + 0][lr + 64] = rb1.x; Bs[0][lc + 1][lr + 64] = rb1.y;
            Bs[0][lc + 2][lr + 64] = rb1.z; Bs[0][lc + 3][lr + 64] = rb1.w;
            __syncthreads();

            const int NT = IN_ / GK;   // 32
            for (int kt = 0; kt < NT; kt++) {
                const int cur = kt & 1, nxt = cur ^ 1;
                if (kt + 1 < NT) {
                    int k0 = (kt + 1) * GK + lc;
                    ra  = __ldcs((const float4*)&x[(m0 + lr) * IN_ + k0]);
                    rb0 = *(const float4*)&W[(size_t)(bn + lr) * IN_ + k0];
                    rb1 = *(const float4*)&W[(size_t)(bn + 64 + lr) * IN_ + k0];
                }
                #pragma unroll
                for (int kk = 0; kk < GK; kk++) {
                    float a[4], bb[8];
                    *(float4*)&a[0]  = *(const float4*)&As[cur][kk][ty * 4];
                    *(float4*)&bb[0] = *(const float4*)&Bs[cur][kk][tx * 8];
                    *(float4*)&bb[4] = *(const float4*)&Bs[cur][kk][tx * 8 + 4];
                    #pragma unroll
                    for (int i = 0; i < 4; i++)
                        #pragma unroll
                        for (int j = 0; j < 8; j++)
                            acc[i][j] = fmaf(a[i], bb[j], acc[i][j]);
                }
                if (kt + 1 < NT) {
                    As[nxt][lc + 0][lr] = ra.x;  As[nxt][lc + 1][lr] = ra.y;
                    As[nxt][lc + 2][lr] = ra.z;  As[nxt][lc + 3][lr] = ra.w;
                    Bs[nxt][lc + 0][lr] = rb0.x; Bs[nxt][lc + 1][lr] = rb0.y;
                    Bs[nxt][lc + 2][lr] = rb0.z; Bs[nxt][lc + 3][lr] = rb0.w;
                    Bs[nxt][lc + 0][lr + 64] = rb1.x; Bs[nxt][lc + 1][lr + 64] = rb1.y;
                    Bs[nxt][lc + 2][lr + 64] = rb1.z; Bs[nxt][lc + 3][lr + 64] = rb1.w;
                }
                __syncthreads();
            }

            float bv[8];
            #pragma unroll
            for (int j = 0; j < 8; j++) bv[j] = bia[bn + tx * 8 + j];
            #pragma unroll
            for (int i = 0; i < 4; i++) {
                size_t m = m0 + ty * 4 + i;
                float4 o0, o1;
                o0.x = acc[i][0] + bv[0]; o0.y = acc[i][1] + bv[1];
                o0.z = acc[i][2] + bv[2]; o0.w = acc[i][3] + bv[3];
                o1.x = acc[i][4] + bv[4]; o1.y = acc[i][5] + bv[5];
                o1.z = acc[i][6] + bv[6]; o1.w = acc[i][7] + bv[7];
                __stcs((float4*)&g_proj[m * H_ + bn + tx * 8],     o0);
                __stcs((float4*)&g_proj[m * H_ + bn + tx * 8 + 4], o1);
            }

            __syncthreads();
            if (tid == 0) {
                __threadfence();
                atomicAdd(&g_flag[b * NCH + tc], 1u);
            }
        }
        return;
    }

    // ======================= scan role (R7 structure, untouched) =======================
    const int b = cta;
    const int h = tid;
    const int wid = tid >> 5, lane = tid & 31;
    const int q = tid >> 6, u = tid & 63;

    const float* pb = g_proj + (size_t)b * T_ * H_;
    float* ob = out + (size_t)b * T_ * H_;
    const float brec = b_rec[h];
    const unsigned* fb = g_flag + b * NCH;

    const char* tbase = (const char*)g_tab
                      + ((size_t)q * 8 * NP * H_ * 4)
                      + (size_t)u * 16;

    if (tid < 8) sbits[0][tid] = 0u;
    __syncthreads();

    if (tid == 0) wait_chunk(fb);
    __syncthreads();

    float mem = 0.0f, spk = 0.0f;
    int buf = 0;
    float p0 = pb[h];
    float p1 = pb[H_ + h];

    for (int t = 0; t < T_; t++) {
        const int tn = t + 2;
        if (tn < T_ && (tn & 63) == 0) {
            if (tid == 0) wait_chunk(fb + (tn >> 6));
            __syncthreads();
        }
        float p2 = (tn < T_) ? pb[(size_t)tn * H_ + h] : 0.0f;

        // ---- phase 1: table-row gather (groups ascending = j ascending) ----
        const unsigned wA = sbits[buf][2 * q];
        const unsigned wB = sbits[buf][2 * q + 1];
        float4 acc = make_float4(0.f, 0.f, 0.f, 0.f);
        #pragma unroll
        for (int i = 0; i < 8; i++) {
            unsigned pat = (i < 4) ? ((wA >> (8 * i)) & 0xFFu)
                                   : ((wB >> (8 * (i - 4))) & 0xFFu);
            const float4 v = *(const float4*)(tbase + (((unsigned)i << 8) + pat) * 1024u);
            acc.x = __fadd_rn(acc.x, v.x);
            acc.y = __fadd_rn(acc.y, v.y);
            acc.z = __fadd_rn(acc.z, v.z);
            acc.w = __fadd_rn(acc.w, v.w);
        }
        sp[buf][q][u] = acc;
        __syncthreads();   // A

        // ---- phase 2: combine quarters + LIF update ----
        const int uu = h >> 2, c = h & 3;
        const float r0 = ((const float*)&sp[buf][0][uu])[c];
        const float r1 = ((const float*)&sp[buf][1][uu])[c];
        const float r2 = ((const float*)&sp[buf][2][uu])[c];
        const float r3 = ((const float*)&sp[buf][3][uu])[c];
        float rec = __fadd_rn(__fadd_rn(r0, r1), __fadd_rn(r2, r3));
        rec = __fadd_rn(rec, brec);

        const float reset = (mem > 1.0f) ? 1.0f : 0.0f;
        const float in_ = __fadd_rn(p0, spk);
        mem = __fsub_rn(__fadd_rn(__fadd_rn(__fmul_rn(0.85f, mem), in_), rec), reset);
        const float s = (mem > 1.0f) ? 1.0f : 0.0f;
        __stcs(&ob[(size_t)t * H_ + h], s);

        const unsigned ball = __ballot_sync(0xFFFFFFFFu, s != 0.0f);
        const int nb = buf ^ 1;
        if (lane == 0) sbits[nb][wid] = ball;
        __syncthreads();   // B

        buf = nb; spk = s;
        p0 = p1; p1 = p2;
    }
}

// ---------------------------------------------------------------------------
extern "C" void kernel_launch(void* const* d_in, const int* in_sizes, int n_in,
                              void* d_out, int out_size) {
    const float* x     = (const float*)d_in[0];
    const float* W_in  = (const float*)d_in[1];
    const float* b_in  = (const float*)d_in[2];
    const float* V     = (const float*)d_in[3];
    const float* b_rec = (const float*)d_in[4];
    float* out = (float*)d_out;

    transpose_V<<<H_, H_>>>(V);
    build_tab<<<NG * NP, H_>>>();
    init_flags<<<1, B_ * NCH>>>();
    fused_kernel<<<NSCAN + NWORK, 256>>>(x, W_in, b_in, b_rec, out);
}

// round 15
// speedup vs baseline: 1.4700x; 1.1004x over previous
#include <cuda_runtime.h>
#include <cstdint>

#define B_  32
#define T_  2048
#define IN_ 512
#define H_  256
#define NG  32      // groups of 8 presynaptic neurons
#define NP  256     // patterns per group (2^8)
#define NCH 32      // T_/64 proj chunks per batch

#define NSCAN 32    // scan CTAs (one per batch)
#define NWORK 116   // persistent GEMM worker CTAs
#define NJOBS 2048  // (B_*T_/GM) * 2 n-halves

// Scratch (allocation-free rule: __device__ globals)
__device__ float g_proj[(size_t)B_ * T_ * H_];        // 64 MB input projection
__device__ float g_Vt[H_ * H_];                       // Vt[j][h] = V[h][j]
__device__ float g_tab[(size_t)NG * NP * H_];         // 8 MB group subset-sum table
__device__ unsigned g_flag[B_ * NCH];                 // producer->consumer chunk flags

// ---------------------------------------------------------------------------
// Setup kernels
// ---------------------------------------------------------------------------
__global__ void transpose_V(const float* __restrict__ V) {
    int j = blockIdx.x;
    int h = threadIdx.x;
    g_Vt[j * H_ + h] = V[h * H_ + j];
}

// tab[g][p][h] = sum_{i: bit i of p} Vt[8g+i][h]   (ascending i)
__global__ void build_tab(void) {
    const int blk = blockIdx.x;          // 0..8191
    const int g = blk >> 8;
    const int p = blk & 255;
    const int h = threadIdx.x;
    float s = 0.0f;
    #pragma unroll
    for (int i = 0; i < 8; i++)
        if ((p >> i) & 1)
            s = __fadd_rn(s, g_Vt[(g * 8 + i) * H_ + h]);
    g_tab[((size_t)g * NP + p) * H_ + h] = s;
}

__global__ void init_flags(void) {
    g_flag[threadIdx.x] = 0u;
}

// ---------------------------------------------------------------------------
// chunk-ready spin (acquire)
// ---------------------------------------------------------------------------
__device__ __forceinline__ void wait_chunk(const unsigned* f) {
    unsigned v;
    do {
        asm volatile("ld.acquire.gpu.global.u32 %0, [%1];"
                     : "=r"(v) : "l"(f) : "memory");
    } while (v < 2u);
}

// ---------------------------------------------------------------------------
// Fused persistent kernel.
//   CTA 0..31   : LIF scan for batch = blockIdx.x (LDG.64 unconditional gather)
//   CTA 32..147 : GEMM workers, grid-stride over NJOBS tile jobs
// ---------------------------------------------------------------------------
#define GM 64
#define GN 128
#define GK 16

__global__ __launch_bounds__(256, 1) void fused_kernel(
    const float* __restrict__ x, const float* __restrict__ W,
    const float* __restrict__ bia,
    const float* __restrict__ b_rec, float* __restrict__ out) {

    __shared__ float As[2][GK][GM];       // GEMM buffers (worker role)
    __shared__ float Bs[2][GK][GN];
    __shared__ float2 sp[4][128];         // [quarter][h-pair] partials (scan role)
    __shared__ unsigned sbits[2][8];      // [buf][warp] ballot words

    const int cta = blockIdx.x;
    const int tid = threadIdx.x;

    if (cta >= NSCAN) {
        // =================== GEMM worker role (R7-identical) ===================
        const int tx = tid & 15;
        const int ty = tid >> 4;
        const int lr = tid >> 2;
        const int lc = (tid & 3) * 4;

        for (int jj = cta - NSCAN; jj < NJOBS; jj += NWORK) {
            const int nt = jj & 1;
            const int b  = (jj >> 1) & 31;
            const int tc = jj >> 6;
            const size_t m0 = (size_t)b * T_ + (size_t)tc * GM;
            const int bn = nt * GN;

            float acc[4][8];
            #pragma unroll
            for (int i = 0; i < 4; i++)
                #pragma unroll
                for (int j = 0; j < 8; j++) acc[i][j] = 0.0f;

            float4 ra, rb0, rb1;
            ra  = *(const float4*)&x[(m0 + lr) * IN_ + lc];
            rb0 = *(const float4*)&W[(size_t)(bn + lr) * IN_ + lc];
            rb1 = *(const float4*)&W[(size_t)(bn + 64 + lr) * IN_ + lc];
            As[0][lc + 0][lr] = ra.x;  As[0][lc + 1][lr] = ra.y;
            As[0][lc + 2][lr] = ra.z;  As[0][lc + 3][lr] = ra.w;
            Bs[0][lc + 0][lr] = rb0.x; Bs[0][lc + 1][lr] = rb0.y;
            Bs[0][lc + 2][lr] = rb0.z; Bs[0][lc + 3][lr] = rb0.w;
            Bs[0][lc + 0][lr + 64] = rb1.x; Bs[0][lc + 1][lr + 64] = rb1.y;
            Bs[0][lc + 2][lr + 64] = rb1.z; Bs[0][lc + 3][lr + 64] = rb1.w;
            __syncthreads();

            const int NT = IN_ / GK;   // 32
            for (int kt = 0; kt < NT; kt++) {
                const int cur = kt & 1, nxt = cur ^ 1;
                if (kt + 1 < NT) {
                    int k0 = (kt + 1) * GK + lc;
                    ra  = *(const float4*)&x[(m0 + lr) * IN_ + k0];
                    rb0 = *(const float4*)&W[(size_t)(bn + lr) * IN_ + k0];
                    rb1 = *(const float4*)&W[(size_t)(bn + 64 + lr) * IN_ + k0];
                }
                #pragma unroll
                for (int kk = 0; kk < GK; kk++) {
                    float a[4], bb[8];
                    *(float4*)&a[0]  = *(const float4*)&As[cur][kk][ty * 4];
                    *(float4*)&bb[0] = *(const float4*)&Bs[cur][kk][tx * 8];
                    *(float4*)&bb[4] = *(const float4*)&Bs[cur][kk][tx * 8 + 4];
                    #pragma unroll
                    for (int i = 0; i < 4; i++)
                        #pragma unroll
                        for (int j = 0; j < 8; j++)
                            acc[i][j] = fmaf(a[i], bb[j], acc[i][j]);
                }
                if (kt + 1 < NT) {
                    As[nxt][lc + 0][lr] = ra.x;  As[nxt][lc + 1][lr] = ra.y;
                    As[nxt][lc + 2][lr] = ra.z;  As[nxt][lc + 3][lr] = ra.w;
                    Bs[nxt][lc + 0][lr] = rb0.x; Bs[nxt][lc + 1][lr] = rb0.y;
                    Bs[nxt][lc + 2][lr] = rb0.z; Bs[nxt][lc + 3][lr] = rb0.w;
                    Bs[nxt][lc + 0][lr + 64] = rb1.x; Bs[nxt][lc + 1][lr + 64] = rb1.y;
                    Bs[nxt][lc + 2][lr + 64] = rb1.z; Bs[nxt][lc + 3][lr + 64] = rb1.w;
                }
                __syncthreads();
            }

            float bv[8];
            #pragma unroll
            for (int j = 0; j < 8; j++) bv[j] = bia[bn + tx * 8 + j];
            #pragma unroll
            for (int i = 0; i < 4; i++) {
                size_t m = m0 + ty * 4 + i;
                float4 o0, o1;
                o0.x = acc[i][0] + bv[0]; o0.y = acc[i][1] + bv[1];
                o0.z = acc[i][2] + bv[2]; o0.w = acc[i][3] + bv[3];
                o1.x = acc[i][4] + bv[4]; o1.y = acc[i][5] + bv[5];
                o1.z = acc[i][6] + bv[6]; o1.w = acc[i][7] + bv[7];
                *(float4*)&g_proj[m * H_ + bn + tx * 8]     = o0;
                *(float4*)&g_proj[m * H_ + bn + tx * 8 + 4] = o1;
            }

            __syncthreads();
            if (tid == 0) {
                __threadfence();
                atomicAdd(&g_flag[b * NCH + tc], 1u);
            }
        }
        return;
    }

    // ============== scan role (unconditional LDG.64 gather) ==============
    // Thread (q = tid>>6, i0 = tid&63) handles h-pairs i0 and i0+64 of
    // quarter q (groups 8q..8q+7). 16 unconditional LDG.64, front-batched
    // (all loads before any FADD) -> MLP 16, 2 lines per warp-instr.
    // Per-pair accumulation is serial over 8 ascending groups -> addition
    // tree bitwise identical to R7.
    const int b = cta;
    const int h = tid;
    const int wid = tid >> 5, lane = tid & 31;
    const int q = tid >> 6, i0 = tid & 63;

    const float* pb = g_proj + (size_t)b * T_ * H_;
    float* ob = out + (size_t)b * T_ * H_;
    const float brec = b_rec[h];
    const unsigned* fb = g_flag + b * NCH;

    // byte base for quarter q at h-pair i0 (second pair at +512B)
    const char* tbase = (const char*)g_tab
                      + ((size_t)q * 8 * NP * H_ * 4)
                      + (size_t)i0 * 8;

    if (tid < 8) sbits[0][tid] = 0u;
    __syncthreads();

    if (tid == 0) wait_chunk(fb);
    __syncthreads();

    float mem = 0.0f, spk = 0.0f;
    int buf = 0;
    float p0 = pb[h];
    float p1 = pb[H_ + h];

    for (int t = 0; t < T_; t++) {
        const int tn = t + 2;
        if (tn < T_ && (tn & 63) == 0) {
            if (tid == 0) wait_chunk(fb + (tn >> 6));
            __syncthreads();
        }
        float p2 = (tn < T_) ? pb[(size_t)tn * H_ + h] : 0.0f;

        // ---- phase 1: 16 unconditional LDG.64, loads first, adds after ----
        const unsigned wA = sbits[buf][2 * q];
        const unsigned wB = sbits[buf][2 * q + 1];
        float2 v0[8], v1[8];
        #pragma unroll
        for (int i = 0; i < 8; i++) {
            const unsigned pat = (i < 4) ? ((wA >> (8 * i)) & 0xFFu)
                                         : ((wB >> (8 * (i - 4))) & 0xFFu);
            const char* rp = tbase + (((unsigned)i << 8) + pat) * 1024u;
            v0[i] = __ldg((const float2*)rp);
            v1[i] = __ldg((const float2*)(rp + 512));
        }
        float2 a0 = make_float2(0.f, 0.f);
        float2 a1 = make_float2(0.f, 0.f);
        #pragma unroll
        for (int i = 0; i < 8; i++) {
            a0.x = __fadd_rn(a0.x, v0[i].x);
            a0.y = __fadd_rn(a0.y, v0[i].y);
            a1.x = __fadd_rn(a1.x, v1[i].x);
            a1.y = __fadd_rn(a1.y, v1[i].y);
        }
        sp[q][i0]      = a0;
        sp[q][i0 + 64] = a1;
        __syncthreads();   // A

        // ---- phase 2: combine quarters + LIF (thread h = neuron h) ----
        const int hp = h >> 1, c = h & 1;
        const float r0 = ((const float*)&sp[0][hp])[c];
        const float r1 = ((const float*)&sp[1][hp])[c];
        const float r2 = ((const float*)&sp[2][hp])[c];
        const float r3 = ((const float*)&sp[3][hp])[c];
        float rec = __fadd_rn(__fadd_rn(r0, r1), __fadd_rn(r2, r3));
        rec = __fadd_rn(rec, brec);

        const float reset = (mem > 1.0f) ? 1.0f : 0.0f;
        const float in_ = __fadd_rn(p0, spk);
        mem = __fsub_rn(__fadd_rn(__fadd_rn(__fmul_rn(0.85f, mem), in_), rec), reset);
        const float s = (mem > 1.0f) ? 1.0f : 0.0f;
        ob[(size_t)t * H_ + h] = s;

        const unsigned ball = __ballot_sync(0xFFFFFFFFu, s != 0.0f);
        const int nb = buf ^ 1;
        if (lane == 0) sbits[nb][wid] = ball;
        __syncthreads();   // B

        buf = nb; spk = s;
        p0 = p1; p1 = p2;
    }
}

// ---------------------------------------------------------------------------
extern "C" void kernel_launch(void* const* d_in, const int* in_sizes, int n_in,
                              void* d_out, int out_size) {
    const float* x     = (const float*)d_in[0];
    const float* W_in  = (const float*)d_in[1];
    const float* b_in  = (const float*)d_in[2];
    const float* V     = (const float*)d_in[3];
    const float* b_rec = (const float*)d_in[4];
    float* out = (float*)d_out;

    transpose_V<<<H_, H_>>>(V);
    build_tab<<<NG * NP, H_>>>();
    init_flags<<<1, B_ * NCH>>>();
    fused_kernel<<<NSCAN + NWORK, 256>>>(x, W_in, b_in, b_rec, out);
}